// round 2
// baseline (speedup 1.0000x reference)
#include <cuda_runtime.h>
#include <cuda_bf16.h>
#include <math.h>

// Problem constants
#define B_   8
#define CIN  64
#define COUT 32
#define HIN  128
#define WIN  128
#define HO   256
#define WO   256
#define ATT  16
#define KNUM 2
#define EPS  1e-5f

#define RATIO 0.49803921568627452f   // 127/255

// Scratch (device globals: no allocation allowed)
__device__ float g_gap[B_ * CIN];               // GAP of (virtually) upsampled x
__device__ float g_weff[B_ * COUT * CIN * 9];   // fully folded per-sample weights
__device__ float g_bias[COUT];                  // folded BN bias

// ---------------------------------------------------------------------------
// K1: GAP of the bilinear-x2 (align_corners) upsample WITHOUT materializing it.
// mean(up(x)) = (1/65536) * sum_{y,x} R[y]*R[x]*x[y][x],
// R[i] = sum over output positions of their interpolation weight into row i.
// One block per (b,c) plane: 512 blocks x 256 threads.
// ---------------------------------------------------------------------------
__global__ void k_gap(const float* __restrict__ x)
{
    __shared__ float sR[HIN];
    __shared__ float red[256];
    int t = threadIdx.x;

    // build R[128] with smem atomics (512 contributions)
    if (t < HIN) sR[t] = 0.0f;
    __syncthreads();
    if (t < HO) {
        float py = (float)t * RATIO;
        int   y0 = (int)py;
        float wy = py - (float)y0;
        int   y1 = min(y0 + 1, HIN - 1);
        atomicAdd(&sR[y0], 1.0f - wy);
        atomicAdd(&sR[y1], wy);
    }
    __syncthreads();

    int bc = blockIdx.x;
    const float* __restrict__ plane = x + (size_t)bc * HIN * WIN;

    float lsum = 0.0f;
    for (int idx = t; idx < HIN * WIN; idx += 256) {
        int y = idx >> 7;
        int c = idx & 127;
        lsum += plane[idx] * sR[y] * sR[c];
    }
    red[t] = lsum;
    __syncthreads();
    for (int s = 128; s > 0; s >>= 1) {
        if (t < s) red[t] += red[t + s];
        __syncthreads();
    }
    if (t == 0)
        g_gap[bc] = red[0] * (1.0f / (float)(HO * WO));
}

// ---------------------------------------------------------------------------
// K2: attention MLP + full weight folding.
// One block per sample b. Produces g_weff[b,co,ci,9] with ch_att (cin),
// fil_att*gamma*invstd (cout), sp_att (tap), k_att (kernel mix) all folded in,
// and g_bias[co] = beta - mean*gamma*invstd.
// ---------------------------------------------------------------------------
__global__ void k_attention(
    const float* __restrict__ fc_w,
    const float* __restrict__ bna_g, const float* __restrict__ bna_b,
    const float* __restrict__ bna_m, const float* __restrict__ bna_v,
    const float* __restrict__ ch_w,  const float* __restrict__ ch_b,
    const float* __restrict__ fil_w, const float* __restrict__ fil_b,
    const float* __restrict__ sp_w,  const float* __restrict__ sp_b,
    const float* __restrict__ k_w,   const float* __restrict__ k_b,
    const float* __restrict__ weight,
    const float* __restrict__ bn_g,  const float* __restrict__ bn_b,
    const float* __restrict__ bn_m,  const float* __restrict__ bn_v)
{
    int b = blockIdx.x;
    int t = threadIdx.x;
    __shared__ float sh[ATT];     // hidden after BN+ReLU
    __shared__ float sch[CIN];    // channel attention
    __shared__ float sfs[COUT];   // fil_att * gamma * invstd
    __shared__ float ssp[9];      // spatial attention
    __shared__ float sraw[KNUM];  // kernel logits
    __shared__ float skk[KNUM];   // kernel softmax

    if (t < ATT) {
        const float* g = g_gap + b * CIN;
        float acc = 0.0f;
        #pragma unroll
        for (int ci = 0; ci < CIN; ci++) acc += fc_w[t * CIN + ci] * g[ci];
        acc = (acc - bna_m[t]) * rsqrtf(bna_v[t] + EPS) * bna_g[t] + bna_b[t];
        sh[t] = fmaxf(acc, 0.0f);
    }
    __syncthreads();

    if (t < CIN) {
        float a = ch_b[t];
        #pragma unroll
        for (int j = 0; j < ATT; j++) a += ch_w[t * ATT + j] * sh[j];
        sch[t] = 1.0f / (1.0f + expf(-a));
    } else if (t < CIN + COUT) {
        int co = t - CIN;
        float a = fil_b[co];
        #pragma unroll
        for (int j = 0; j < ATT; j++) a += fil_w[co * ATT + j] * sh[j];
        float fil = 1.0f / (1.0f + expf(-a));
        sfs[co] = fil * bn_g[co] * rsqrtf(bn_v[co] + EPS);
    } else if (t < CIN + COUT + 9) {
        int q = t - CIN - COUT;
        float a = sp_b[q];
        #pragma unroll
        for (int j = 0; j < ATT; j++) a += sp_w[q * ATT + j] * sh[j];
        ssp[q] = 1.0f / (1.0f + expf(-a));
    } else if (t < CIN + COUT + 9 + KNUM) {
        int k = t - CIN - COUT - 9;
        float a = k_b[k];
        #pragma unroll
        for (int j = 0; j < ATT; j++) a += k_w[k * ATT + j] * sh[j];
        sraw[k] = a;
    }
    __syncthreads();
    if (t == 0) {
        float m  = fmaxf(sraw[0], sraw[1]);
        float e0 = expf(sraw[0] - m);
        float e1 = expf(sraw[1] - m);
        float inv = 1.0f / (e0 + e1);
        skk[0] = e0 * inv;
        skk[1] = e1 * inv;
    }
    __syncthreads();

    const int WSZ = COUT * CIN * 9;   // 18432
    float* wout = g_weff + b * WSZ;
    for (int idx = t; idx < WSZ; idx += blockDim.x) {
        int co  = idx / (CIN * 9);
        int rem = idx % (CIN * 9);
        int ci  = rem / 9;
        int q   = rem % 9;
        float w = skk[0] * weight[idx] + skk[1] * weight[WSZ + idx];
        wout[idx] = w * ssp[q] * sch[ci] * sfs[co];
    }
    if (b == 0 && t < COUT)
        g_bias[t] = bn_b[t] - bn_m[t] * bn_g[t] * rsqrtf(bn_v[t] + EPS);
}

// ---------------------------------------------------------------------------
// K3: fused bilinear-upsample + direct 3x3 conv (per-sample folded weights)
//     + bias + exact GELU.
// Block: 1 sample, 32 cout, 8-row x 64-col spatial tile. 256 threads.
// Thread: 8 cout x (1x8 pixel strip) = 64 accumulators.
// The upsampled activation is computed on-the-fly during the smem tile fill
// (4 L2-resident loads of the 33MB original input per element).
// ---------------------------------------------------------------------------
#define CI_CHUNK 8
#define TH 8
#define TW 64

__global__ void __launch_bounds__(256, 2) k_conv(const float* __restrict__ x,
                                                 float* __restrict__ out)
{
    __shared__ float sX[CI_CHUNK][TH + 2][TW + 4];   // 10 x 68 padded
    __shared__ float sW[CI_CHUNK][COUT][9];

    int b    = blockIdx.z;
    int row0 = blockIdx.y * TH;
    int col0 = blockIdx.x * TW;
    int tid  = threadIdx.x;
    int tc   = tid >> 6;          // 0..3: cout group (warp-uniform)
    int tp   = tid & 63;
    int rowt = tp >> 3;           // 0..7
    int colt = (tp & 7) * 8;      // 0..56

    float acc[8][8];
    #pragma unroll
    for (int i = 0; i < 8; i++)
        #pragma unroll
        for (int p = 0; p < 8; p++) acc[i][p] = 0.0f;

    const float* __restrict__ weffb = g_weff + b * (COUT * CIN * 9);

    for (int cc = 0; cc < CIN; cc += CI_CHUNK) {
        // load weight chunk: 8*32*9 = 2304
        for (int i = tid; i < CI_CHUNK * COUT * 9; i += 256) {
            int ci  = i / (COUT * 9);
            int rem = i % (COUT * 9);
            int co  = rem / 9;
            int q   = rem % 9;
            sW[ci][co][q] = weffb[co * (CIN * 9) + (cc + ci) * 9 + q];
        }
        // fill input tile + halo (8 x 10 x 66), computing the bilinear
        // upsample on the fly from the original 128x128 planes.
        for (int i = tid; i < CI_CHUNK * (TH + 2) * (TW + 2); i += 256) {
            int ci  = i / ((TH + 2) * (TW + 2));
            int rem = i % ((TH + 2) * (TW + 2));
            int r   = rem / (TW + 2);
            int c   = rem % (TW + 2);
            int gr  = row0 - 1 + r;            // output-space row (-1..256)
            int gc  = col0 - 1 + c;
            float v = 0.0f;
            if ((unsigned)gr < (unsigned)HO && (unsigned)gc < (unsigned)WO) {
                float py = (float)gr * RATIO;
                int   y0 = (int)py;
                float wy = py - (float)y0;
                int   y1 = min(y0 + 1, HIN - 1);
                float px = (float)gc * RATIO;
                int   x0 = (int)px;
                float wx = px - (float)x0;
                int   x1 = min(x0 + 1, WIN - 1);
                const float* __restrict__ p =
                    x + ((size_t)b * CIN + cc + ci) * (HIN * WIN);
                float a  = __ldg(p + y0 * WIN + x0);
                float bb = __ldg(p + y0 * WIN + x1);
                float cv = __ldg(p + y1 * WIN + x0);
                float d  = __ldg(p + y1 * WIN + x1);
                float v0 = a  * (1.0f - wy) + cv * wy;   // rows first
                float v1 = bb * (1.0f - wy) + d  * wy;
                v = v0 * (1.0f - wx) + v1 * wx;          // then cols
            }
            sX[ci][r][c] = v;
        }
        __syncthreads();

        #pragma unroll 1
        for (int ci = 0; ci < CI_CHUNK; ci++) {
            #pragma unroll
            for (int ky = 0; ky < 3; ky++) {
                float xr[10];
                #pragma unroll
                for (int j = 0; j < 10; j++)
                    xr[j] = sX[ci][rowt + ky][colt + j];
                #pragma unroll
                for (int kx = 0; kx < 3; kx++) {
                    float wv[8];
                    #pragma unroll
                    for (int i = 0; i < 8; i++)
                        wv[i] = sW[ci][tc * 8 + i][ky * 3 + kx];
                    #pragma unroll
                    for (int i = 0; i < 8; i++)
                        #pragma unroll
                        for (int p = 0; p < 8; p++)
                            acc[i][p] = fmaf(wv[i], xr[p + kx], acc[i][p]);
                }
            }
        }
        __syncthreads();
    }

    // epilogue: bias + exact-erf GELU
    #pragma unroll
    for (int i = 0; i < 8; i++) {
        int co = tc * 8 + i;
        float bias = g_bias[co];
        size_t base = (((size_t)b * COUT + co) * HO + (row0 + rowt)) * WO
                      + col0 + colt;
        #pragma unroll
        for (int p = 0; p < 8; p++) {
            float v = acc[i][p] + bias;
            out[base + p] = 0.5f * v * (1.0f + erff(v * 0.70710678118654752f));
        }
    }
}

// ---------------------------------------------------------------------------
extern "C" void kernel_launch(void* const* d_in, const int* in_sizes, int n_in,
                              void* d_out, int out_size)
{
    const float* x      = (const float*)d_in[0];
    const float* fc_w   = (const float*)d_in[1];
    const float* bna_g  = (const float*)d_in[2];
    const float* bna_b  = (const float*)d_in[3];
    const float* bna_m  = (const float*)d_in[4];
    const float* bna_v  = (const float*)d_in[5];
    const float* ch_w   = (const float*)d_in[6];
    const float* ch_b   = (const float*)d_in[7];
    const float* fil_w  = (const float*)d_in[8];
    const float* fil_b  = (const float*)d_in[9];
    const float* sp_w   = (const float*)d_in[10];
    const float* sp_b   = (const float*)d_in[11];
    const float* k_w    = (const float*)d_in[12];
    const float* k_b    = (const float*)d_in[13];
    const float* weight = (const float*)d_in[14];
    const float* bn_g   = (const float*)d_in[15];
    const float* bn_b   = (const float*)d_in[16];
    const float* bn_m   = (const float*)d_in[17];
    const float* bn_v   = (const float*)d_in[18];

    k_gap<<<B_ * CIN, 256>>>(x);
    k_attention<<<B_, 256>>>(fc_w, bna_g, bna_b, bna_m, bna_v,
                             ch_w, ch_b, fil_w, fil_b, sp_w, sp_b, k_w, k_b,
                             weight, bn_g, bn_b, bn_m, bn_v);
    k_conv<<<dim3(WO / TW, HO / TH, B_), 256>>>(x, (float*)d_out);
}